// round 3
// baseline (speedup 1.0000x reference)
#include <cuda_runtime.h>

#define HID 128
#define NMAX 50000
#define EMAX 500000

// ---------------- device scratch (no allocations allowed) ----------------
__device__ float g_agg[(size_t)NMAX * HID];
__device__ float g_inv[NMAX];
__device__ int   g_indeg[NMAX];
__device__ int   g_eperm[EMAX];
__device__ int   g_nperm[NMAX];
__device__ int   g_ecnt[8], g_eoff[8], g_ecur[8];
__device__ int   g_ncnt[8], g_noff[8], g_ncur[8];

// ---------------- packed f32x2 helpers ----------------
static __device__ __forceinline__ unsigned long long pk(float x, float y){
    unsigned long long r;
    asm("mov.b64 %0, {%1, %2};" : "=l"(r) : "f"(x), "f"(y));
    return r;
}
static __device__ __forceinline__ unsigned long long pk2(float a){ return pk(a, a); }
static __device__ __forceinline__ unsigned long long ffma2(unsigned long long a, unsigned long long b, unsigned long long c){
    unsigned long long d;
    asm("fma.rn.f32x2 %0, %1, %2, %3;" : "=l"(d) : "l"(a), "l"(b), "l"(c));
    return d;
}
static __device__ __forceinline__ float lo2(unsigned long long v){ return __uint_as_float((unsigned)v); }
static __device__ __forceinline__ float hi2(unsigned long long v){ return __uint_as_float((unsigned)(v >> 32)); }

// ---------------- bucketing kernels ----------------
__global__ void k_zero(int nagg, int N){
    int i  = blockIdx.x * blockDim.x + threadIdx.x;
    int st = gridDim.x * blockDim.x;
    for (int j = i; j < nagg; j += st) g_agg[j] = 0.f;
    for (int j = i; j < N;    j += st) g_indeg[j] = 0;
    if (i < 8){ g_ecnt[i] = 0; g_ncnt[i] = 0; }
}

__global__ void k_count(const int* __restrict__ ei, const int* __restrict__ depth, int N, int E){
    int i = blockIdx.x * blockDim.x + threadIdx.x;
    if (i < E){
        int dst = ei[E + i];
        atomicAdd(&g_ecnt[depth[dst]], 1);
        atomicAdd(&g_indeg[dst], 1);
    }
    if (i < N){
        atomicAdd(&g_ncnt[depth[i]], 1);
    }
}

__global__ void k_scan(){
    int e = 0, n = 0;
    for (int d = 0; d < 8; ++d){
        g_eoff[d] = e; g_ecur[d] = e; e += g_ecnt[d];
        g_noff[d] = n; g_ncur[d] = n; n += g_ncnt[d];
    }
}

__global__ void k_scatter(const int* __restrict__ ei, const int* __restrict__ depth, int N, int E){
    int i = blockIdx.x * blockDim.x + threadIdx.x;
    if (i < E){
        int dst = ei[E + i];
        int p = atomicAdd(&g_ecur[depth[dst]], 1);
        g_eperm[p] = i;
    }
    if (i < N){
        int p = atomicAdd(&g_ncur[depth[i]], 1);
        g_nperm[p] = i;
        int c = g_indeg[i];
        g_inv[i] = 1.0f / (float)(c > 0 ? c : 1);
    }
}

// ---------------- GEMM building blocks ----------------
// A is i-major in shared: A[(i0+ii)*LDA + k], broadcast-friendly reads.
// Ws is one staged 16 x 128 slab of the (row-major K x 128) weight.
template<int LDA>
static __device__ __forceinline__ void mm16(const float* __restrict__ A, const float* __restrict__ Ws,
                                            int i0, int j0, unsigned long long acc[4][4]){
    #pragma unroll
    for (int kk = 0; kk < 16; ++kk){
        const float* wr = Ws + kk * HID + j0;
        ulonglong2 wA = *(const ulonglong2*)(wr);
        ulonglong2 wB = *(const ulonglong2*)(wr + 4);
        #pragma unroll
        for (int ii = 0; ii < 4; ++ii){
            unsigned long long a2 = pk2(A[(i0 + ii) * LDA + kk]);
            acc[ii][0] = ffma2(a2, wA.x, acc[ii][0]);
            acc[ii][1] = ffma2(a2, wA.y, acc[ii][1]);
            acc[ii][2] = ffma2(a2, wB.x, acc[ii][2]);
            acc[ii][3] = ffma2(a2, wB.y, acc[ii][3]);
        }
    }
}

// Stage rows [k0, k0+16) of W (K x 128 row-major) into Ws; zero-fill rows >= K.
static __device__ __forceinline__ void stage_w(float* Ws, const float* __restrict__ W, int k0, int K, int tid){
    #pragma unroll
    for (int r = 0; r < 2; ++r){
        int idx = tid + (r << 8);           // float4 index 0..511
        int kr  = idx >> 5;                 // slab row 0..15
        int c4  = (idx & 31) << 2;          // column 0..124
        int k   = k0 + kr;
        float4 v = make_float4(0.f, 0.f, 0.f, 0.f);
        if (k < K) v = *(const float4*)(W + (size_t)k * HID + c4);
        *(float4*)(Ws + kr * HID + c4) = v;
    }
}

static __device__ __forceinline__ void init_acc_bias(const float* __restrict__ b, int j0, unsigned long long acc[4][4]){
    float4 b0 = *(const float4*)(b + j0);
    float4 b1 = *(const float4*)(b + j0 + 4);
    unsigned long long p0 = pk(b0.x, b0.y), p1 = pk(b0.z, b0.w);
    unsigned long long p2 = pk(b1.x, b1.y), p3 = pk(b1.z, b1.w);
    #pragma unroll
    for (int ii = 0; ii < 4; ++ii){
        acc[ii][0] = p0; acc[ii][1] = p1; acc[ii][2] = p2; acc[ii][3] = p3;
    }
}

// ---------------- projection: h = x @ pw + pb ----------------
#define SMEM_PROJ ((64*132 + 16*128) * 4)
__global__ __launch_bounds__(256) void k_proj(const float* __restrict__ x, const float* __restrict__ pw,
                                              const float* __restrict__ pb, float* __restrict__ h, int N){
    extern __shared__ float sm[];
    const int LDA = 132;
    float* As = sm;                 // 64 x 132
    float* Ws = sm + 64 * LDA;      // 16 x 128
    int tid = threadIdx.x;
    int r0  = blockIdx.x * 64;
    {
        int i = tid >> 2, sub = tid & 3;
        int row = r0 + i;
        const float4* xr = (const float4*)(x + (size_t)(row < N ? row : 0) * HID);
        #pragma unroll
        for (int c = 0; c < 8; ++c){
            int k4 = (sub << 3) + c;
            *(float4*)(As + i * LDA + (k4 << 2)) = xr[k4];
        }
    }
    int ti = tid & 15, tj = tid >> 4;
    int i0 = tj << 2, j0 = ti << 3;
    unsigned long long acc[4][4];
    init_acc_bias(pb, j0, acc);
    for (int s = 0; s < 8; ++s){
        __syncthreads();
        stage_w(Ws, pw, s * 16, 128, tid);
        __syncthreads();
        mm16<132>(As + s * 16, Ws, i0, j0, acc);
    }
    #pragma unroll
    for (int ii = 0; ii < 4; ++ii){
        int row = r0 + i0 + ii;
        if (row < N){
            float* hr = h + (size_t)row * HID + j0;
            #pragma unroll
            for (int p = 0; p < 4; ++p)
                *(float2*)(hr + (p << 1)) = make_float2(lo2(acc[ii][p]), hi2(acc[ii][p]));
        }
    }
}

// ---------------- message MLP per level (only edges with dst_depth == lvl) ----------------
#define SMEM_MSG ((64*144 + 64*132 + 16*128) * 4 + 64 * 4)
__global__ __launch_bounds__(256, 2) void k_msg(const float* __restrict__ h, const int* __restrict__ ei,
                                                const float* __restrict__ eattr,
                                                const float* __restrict__ mw1, const float* __restrict__ mb1,
                                                const float* __restrict__ mw2, const float* __restrict__ mb2,
                                                int E, int lvl){
    extern __shared__ float sm[];
    const int LDA = 144;            // K=129 padded to 144 (9 slabs of 16)
    const int LDT = 132;
    float* As = sm;                 // 64 x 144
    float* T  = As + 64 * LDA;      // 64 x 132
    float* Ws = T + 64 * LDT;       // 16 x 128
    int* sdst = (int*)(Ws + 16 * HID);  // 64

    int tid = threadIdx.x;
    int ti = tid & 15, tj = tid >> 4;
    int i0 = tj << 2, j0 = ti << 3;

    int cnt  = g_ecnt[lvl];
    int base = g_eoff[lvl];
    int ntiles = (cnt + 63) >> 6;

    for (int t = blockIdx.x; t < ntiles; t += gridDim.x){
        __syncthreads();
        // gather A = [h[src] | edge_attr | zero-pad]
        {
            int i = tid >> 2, sub = tid & 3;
            int p = t * 64 + i;
            int e = (p < cnt) ? g_eperm[base + p] : -1;
            int src = (e >= 0) ? ei[e] : 0;
            const float4* hr = (const float4*)(h + (size_t)src * HID);
            #pragma unroll
            for (int c = 0; c < 8; ++c){
                int k4 = (sub << 3) + c;
                *(float4*)(As + i * LDA + (k4 << 2)) = hr[k4];
            }
            if (sub == 0){
                As[i * LDA + 128] = (e >= 0) ? eattr[e] : 0.f;
                #pragma unroll
                for (int c = 129; c < 144; ++c) As[i * LDA + c] = 0.f;
                sdst[i] = (e >= 0) ? ei[E + e] : -1;
            }
        }
        __syncthreads();
        // layer 1: K = 129
        unsigned long long acc[4][4];
        init_acc_bias(mb1, j0, acc);
        for (int s = 0; s < 9; ++s){
            __syncthreads();
            stage_w(Ws, mw1, s * 16, 129, tid);
            __syncthreads();
            mm16<144>(As + s * 16, Ws, i0, j0, acc);
        }
        // relu -> T (i-major)
        #pragma unroll
        for (int ii = 0; ii < 4; ++ii){
            float* trow = T + (i0 + ii) * LDT + j0;
            #pragma unroll
            for (int p = 0; p < 4; ++p){
                trow[2*p]   = fmaxf(lo2(acc[ii][p]), 0.f);
                trow[2*p+1] = fmaxf(hi2(acc[ii][p]), 0.f);
            }
        }
        // layer 2: K = 128
        init_acc_bias(mb2, j0, acc);
        for (int s = 0; s < 8; ++s){
            __syncthreads();
            stage_w(Ws, mw2, s * 16, 128, tid);
            __syncthreads();
            mm16<132>(T + s * 16, Ws, i0, j0, acc);
        }
        // epilogue: relu + atomic accumulate into g_agg[dst]
        #pragma unroll
        for (int ii = 0; ii < 4; ++ii){
            int i = i0 + ii;
            int p = t * 64 + i;
            if (p < cnt){
                int dst = sdst[i];
                float* arow = g_agg + (size_t)dst * HID + j0;
                #pragma unroll
                for (int q = 0; q < 4; ++q){
                    atomicAdd(arow + 2*q,     fmaxf(lo2(acc[ii][q]), 0.f));
                    atomicAdd(arow + 2*q + 1, fmaxf(hi2(acc[ii][q]), 0.f));
                }
            }
        }
    }
}

// ---------------- node update per level (only nodes with depth == lvl) ----------------
#define SMEM_UPD ((64*260 + 64*132 + 16*128) * 4 + 64 * 4)
__global__ __launch_bounds__(256, 2) void k_upd(float* __restrict__ h,
                                                const float* __restrict__ uw1, const float* __restrict__ ub1,
                                                const float* __restrict__ uw2, const float* __restrict__ ub2,
                                                int lvl){
    extern __shared__ float sm[];
    const int LDA = 260;            // K=256, pad +4
    const int LDT = 132;
    float* As = sm;                 // 64 x 260
    float* T  = As + 64 * LDA;      // 64 x 132
    float* Ws = T + 64 * LDT;       // 16 x 128
    int* snode = (int*)(Ws + 16 * HID);

    int tid = threadIdx.x;
    int ti = tid & 15, tj = tid >> 4;
    int i0 = tj << 2, j0 = ti << 3;

    int cnt  = g_ncnt[lvl];
    int base = g_noff[lvl];
    int ntiles = (cnt + 63) >> 6;

    for (int t = blockIdx.x; t < ntiles; t += gridDim.x){
        __syncthreads();
        // gather A = [h[v] | agg[v] * inv[v]]
        {
            int i = tid >> 2, sub = tid & 3;
            int p = t * 64 + i;
            int v = (p < cnt) ? g_nperm[base + p] : 0;
            float inv = g_inv[v];
            const float4* hr = (const float4*)(h + (size_t)v * HID);
            const float4* ar = (const float4*)(g_agg + (size_t)v * HID);
            #pragma unroll
            for (int c = 0; c < 8; ++c){
                int k4 = (sub << 3) + c;
                *(float4*)(As + i * LDA + (k4 << 2)) = hr[k4];
                float4 a = ar[k4];
                a.x *= inv; a.y *= inv; a.z *= inv; a.w *= inv;
                *(float4*)(As + i * LDA + 128 + (k4 << 2)) = a;
            }
            if (sub == 0) snode[i] = (p < cnt) ? v : -1;
        }
        __syncthreads();
        // layer 1: K = 256
        unsigned long long acc[4][4];
        init_acc_bias(ub1, j0, acc);
        for (int s = 0; s < 16; ++s){
            __syncthreads();
            stage_w(Ws, uw1, s * 16, 256, tid);
            __syncthreads();
            mm16<260>(As + s * 16, Ws, i0, j0, acc);
        }
        #pragma unroll
        for (int ii = 0; ii < 4; ++ii){
            float* trow = T + (i0 + ii) * LDT + j0;
            #pragma unroll
            for (int p = 0; p < 4; ++p){
                trow[2*p]   = fmaxf(lo2(acc[ii][p]), 0.f);
                trow[2*p+1] = fmaxf(hi2(acc[ii][p]), 0.f);
            }
        }
        // layer 2: K = 128
        init_acc_bias(ub2, j0, acc);
        for (int s = 0; s < 8; ++s){
            __syncthreads();
            stage_w(Ws, uw2, s * 16, 128, tid);
            __syncthreads();
            mm16<132>(T + s * 16, Ws, i0, j0, acc);
        }
        // epilogue: relu -> overwrite h[v]
        #pragma unroll
        for (int ii = 0; ii < 4; ++ii){
            int v = snode[i0 + ii];
            if (v >= 0){
                float* hr = h + (size_t)v * HID + j0;
                #pragma unroll
                for (int p = 0; p < 4; ++p)
                    *(float2*)(hr + (p << 1)) = make_float2(fmaxf(lo2(acc[ii][p]), 0.f),
                                                            fmaxf(hi2(acc[ii][p]), 0.f));
            }
        }
    }
}

// ---------------- host launch ----------------
extern "C" void kernel_launch(void* const* d_in, const int* in_sizes, int n_in,
                              void* d_out, int out_size){
    const float* x     = (const float*)d_in[0];
    const int*   ei    = (const int*)  d_in[1];
    const float* eattr = (const float*)d_in[2];
    const int*   depth = (const int*)  d_in[3];
    const float* pw    = (const float*)d_in[4];
    const float* pb    = (const float*)d_in[5];
    const float* mw1   = (const float*)d_in[6];
    const float* mb1   = (const float*)d_in[7];
    const float* mw2   = (const float*)d_in[8];
    const float* mb2   = (const float*)d_in[9];
    const float* uw1   = (const float*)d_in[10];
    const float* ub1   = (const float*)d_in[11];
    const float* uw2   = (const float*)d_in[12];
    const float* ub2   = (const float*)d_in[13];
    float* h = (float*)d_out;

    int N = in_sizes[3];       // depth has N elements
    int E = in_sizes[2];       // edge_attr has E elements (EDGE_DIM = 1)

    cudaFuncSetAttribute(k_proj, cudaFuncAttributeMaxDynamicSharedMemorySize, SMEM_PROJ);
    cudaFuncSetAttribute(k_msg,  cudaFuncAttributeMaxDynamicSharedMemorySize, SMEM_MSG);
    cudaFuncSetAttribute(k_upd,  cudaFuncAttributeMaxDynamicSharedMemorySize, SMEM_UPD);

    k_zero<<<1024, 256>>>(N * HID, N);

    int mx = (E > N) ? E : N;
    int gb = (mx + 255) / 256;
    k_count<<<gb, 256>>>(ei, depth, N, E);
    k_scan<<<1, 1>>>();
    k_scatter<<<gb, 256>>>(ei, depth, N, E);

    k_proj<<<(N + 63) / 64, 256, SMEM_PROJ>>>(x, pw, pb, h, N);

    for (int d = 1; d <= 4; ++d){
        k_msg<<<1184, 256, SMEM_MSG>>>(h, ei, eattr, mw1, mb1, mw2, mb2, E, d);
        k_upd<<<512, 256, SMEM_UPD>>>(h, uw1, ub1, uw2, ub2, d);
    }
}

// round 4
// speedup vs baseline: 1.0019x; 1.0019x over previous
#include <cuda_runtime.h>

#define HID 128
#define NMAX 50000
#define EMAX 500000

// ---------------- device scratch (no allocations allowed) ----------------
__device__ float g_agg[(size_t)NMAX * HID];
__device__ float g_inv[NMAX];
__device__ int   g_indeg[NMAX];
__device__ int   g_eperm[EMAX];
__device__ int   g_nperm[NMAX];
__device__ int   g_ecnt[8], g_eoff[8], g_ecur[8];
__device__ int   g_ncnt[8], g_noff[8], g_ncur[8];

// ---------------- packed f32x2 helpers ----------------
static __device__ __forceinline__ unsigned long long pk(float x, float y){
    unsigned long long r;
    asm("mov.b64 %0, {%1, %2};" : "=l"(r) : "f"(x), "f"(y));
    return r;
}
static __device__ __forceinline__ unsigned long long pk2(float a){ return pk(a, a); }
static __device__ __forceinline__ unsigned long long ffma2(unsigned long long a, unsigned long long b, unsigned long long c){
    unsigned long long d;
    asm("fma.rn.f32x2 %0, %1, %2, %3;" : "=l"(d) : "l"(a), "l"(b), "l"(c));
    return d;
}
static __device__ __forceinline__ float lo2(unsigned long long v){ return __uint_as_float((unsigned)v); }
static __device__ __forceinline__ float hi2(unsigned long long v){ return __uint_as_float((unsigned)(v >> 32)); }

// ---------------- bucketing kernels ----------------
__global__ void k_zero(int nagg, int N){
    int i  = blockIdx.x * blockDim.x + threadIdx.x;
    int st = gridDim.x * blockDim.x;
    for (int j = i; j < nagg; j += st) g_agg[j] = 0.f;
    for (int j = i; j < N;    j += st) g_indeg[j] = 0;
    if (i < 8){ g_ecnt[i] = 0; g_ncnt[i] = 0; }
}

__global__ void k_count(const int* __restrict__ ei, const int* __restrict__ depth, int N, int E){
    int i = blockIdx.x * blockDim.x + threadIdx.x;
    if (i < E){
        int dst = ei[E + i];
        atomicAdd(&g_ecnt[depth[dst]], 1);
        atomicAdd(&g_indeg[dst], 1);
    }
    if (i < N){
        atomicAdd(&g_ncnt[depth[i]], 1);
    }
}

__global__ void k_scan(){
    int e = 0, n = 0;
    for (int d = 0; d < 8; ++d){
        g_eoff[d] = e; g_ecur[d] = e; e += g_ecnt[d];
        g_noff[d] = n; g_ncur[d] = n; n += g_ncnt[d];
    }
}

__global__ void k_scatter(const int* __restrict__ ei, const int* __restrict__ depth, int N, int E){
    int i = blockIdx.x * blockDim.x + threadIdx.x;
    if (i < E){
        int dst = ei[E + i];
        int p = atomicAdd(&g_ecur[depth[dst]], 1);
        g_eperm[p] = i;
    }
    if (i < N){
        int p = atomicAdd(&g_ncur[depth[i]], 1);
        g_nperm[p] = i;
        int c = g_indeg[i];
        g_inv[i] = 1.0f / (float)(c > 0 ? c : 1);
    }
}

// ---------------- GEMM building blocks ----------------
// A is i-major in shared: A[(i0+ii)*LDA + k], broadcast-friendly reads.
// Ws is one staged 16 x 128 slab of the (row-major K x 128) weight.
template<int LDA>
static __device__ __forceinline__ void mm16(const float* __restrict__ A, const float* __restrict__ Ws,
                                            int i0, int j0, unsigned long long acc[4][4]){
    #pragma unroll
    for (int kk = 0; kk < 16; ++kk){
        const float* wr = Ws + kk * HID + j0;
        ulonglong2 wA = *(const ulonglong2*)(wr);
        ulonglong2 wB = *(const ulonglong2*)(wr + 4);
        #pragma unroll
        for (int ii = 0; ii < 4; ++ii){
            unsigned long long a2 = pk2(A[(i0 + ii) * LDA + kk]);
            acc[ii][0] = ffma2(a2, wA.x, acc[ii][0]);
            acc[ii][1] = ffma2(a2, wA.y, acc[ii][1]);
            acc[ii][2] = ffma2(a2, wB.x, acc[ii][2]);
            acc[ii][3] = ffma2(a2, wB.y, acc[ii][3]);
        }
    }
}

// Stage rows [k0, k0+16) of W (K x 128 row-major) into Ws; zero-fill rows >= K.
static __device__ __forceinline__ void stage_w(float* Ws, const float* __restrict__ W, int k0, int K, int tid){
    #pragma unroll
    for (int r = 0; r < 2; ++r){
        int idx = tid + (r << 8);           // float4 index 0..511
        int kr  = idx >> 5;                 // slab row 0..15
        int c4  = (idx & 31) << 2;          // column 0..124
        int k   = k0 + kr;
        float4 v = make_float4(0.f, 0.f, 0.f, 0.f);
        if (k < K) v = *(const float4*)(W + (size_t)k * HID + c4);
        *(float4*)(Ws + kr * HID + c4) = v;
    }
}

static __device__ __forceinline__ void init_acc_bias(const float* __restrict__ b, int j0, unsigned long long acc[4][4]){
    float4 b0 = *(const float4*)(b + j0);
    float4 b1 = *(const float4*)(b + j0 + 4);
    unsigned long long p0 = pk(b0.x, b0.y), p1 = pk(b0.z, b0.w);
    unsigned long long p2 = pk(b1.x, b1.y), p3 = pk(b1.z, b1.w);
    #pragma unroll
    for (int ii = 0; ii < 4; ++ii){
        acc[ii][0] = p0; acc[ii][1] = p1; acc[ii][2] = p2; acc[ii][3] = p3;
    }
}

// ---------------- projection: h = x @ pw + pb ----------------
#define SMEM_PROJ ((64*132 + 16*128) * 4)
__global__ __launch_bounds__(256) void k_proj(const float* __restrict__ x, const float* __restrict__ pw,
                                              const float* __restrict__ pb, float* __restrict__ h, int N){
    extern __shared__ float sm[];
    const int LDA = 132;
    float* As = sm;                 // 64 x 132
    float* Ws = sm + 64 * LDA;      // 16 x 128
    int tid = threadIdx.x;
    int r0  = blockIdx.x * 64;
    {
        int i = tid >> 2, sub = tid & 3;
        int row = r0 + i;
        const float4* xr = (const float4*)(x + (size_t)(row < N ? row : 0) * HID);
        #pragma unroll
        for (int c = 0; c < 8; ++c){
            int k4 = (sub << 3) + c;
            *(float4*)(As + i * LDA + (k4 << 2)) = xr[k4];
        }
    }
    int ti = tid & 15, tj = tid >> 4;
    int i0 = tj << 2, j0 = ti << 3;
    unsigned long long acc[4][4];
    init_acc_bias(pb, j0, acc);
    for (int s = 0; s < 8; ++s){
        __syncthreads();
        stage_w(Ws, pw, s * 16, 128, tid);
        __syncthreads();
        mm16<132>(As + s * 16, Ws, i0, j0, acc);
    }
    #pragma unroll
    for (int ii = 0; ii < 4; ++ii){
        int row = r0 + i0 + ii;
        if (row < N){
            float* hr = h + (size_t)row * HID + j0;
            #pragma unroll
            for (int p = 0; p < 4; ++p)
                *(float2*)(hr + (p << 1)) = make_float2(lo2(acc[ii][p]), hi2(acc[ii][p]));
        }
    }
}

// ---------------- message MLP per level (only edges with dst_depth == lvl) ----------------
#define SMEM_MSG ((64*144 + 64*132 + 16*128) * 4 + 64 * 4)
__global__ __launch_bounds__(256, 2) void k_msg(const float* __restrict__ h, const int* __restrict__ ei,
                                                const float* __restrict__ eattr,
                                                const float* __restrict__ mw1, const float* __restrict__ mb1,
                                                const float* __restrict__ mw2, const float* __restrict__ mb2,
                                                int E, int lvl){
    extern __shared__ float sm[];
    const int LDA = 144;            // K=129 padded to 144 (9 slabs of 16)
    const int LDT = 132;
    float* As = sm;                 // 64 x 144
    float* T  = As + 64 * LDA;      // 64 x 132
    float* Ws = T + 64 * LDT;       // 16 x 128
    int* sdst = (int*)(Ws + 16 * HID);  // 64

    int tid = threadIdx.x;
    int ti = tid & 15, tj = tid >> 4;
    int i0 = tj << 2, j0 = ti << 3;

    int cnt  = g_ecnt[lvl];
    int base = g_eoff[lvl];
    int ntiles = (cnt + 63) >> 6;

    for (int t = blockIdx.x; t < ntiles; t += gridDim.x){
        __syncthreads();
        // gather A = [h[src] | edge_attr | zero-pad]
        {
            int i = tid >> 2, sub = tid & 3;
            int p = t * 64 + i;
            int e = (p < cnt) ? g_eperm[base + p] : -1;
            int src = (e >= 0) ? ei[e] : 0;
            const float4* hr = (const float4*)(h + (size_t)src * HID);
            #pragma unroll
            for (int c = 0; c < 8; ++c){
                int k4 = (sub << 3) + c;
                *(float4*)(As + i * LDA + (k4 << 2)) = hr[k4];
            }
            if (sub == 0){
                As[i * LDA + 128] = (e >= 0) ? eattr[e] : 0.f;
                #pragma unroll
                for (int c = 129; c < 144; ++c) As[i * LDA + c] = 0.f;
                sdst[i] = (e >= 0) ? ei[E + e] : -1;
            }
        }
        __syncthreads();
        // layer 1: K = 129
        unsigned long long acc[4][4];
        init_acc_bias(mb1, j0, acc);
        for (int s = 0; s < 9; ++s){
            __syncthreads();
            stage_w(Ws, mw1, s * 16, 129, tid);
            __syncthreads();
            mm16<144>(As + s * 16, Ws, i0, j0, acc);
        }
        // relu -> T (i-major)
        #pragma unroll
        for (int ii = 0; ii < 4; ++ii){
            float* trow = T + (i0 + ii) * LDT + j0;
            #pragma unroll
            for (int p = 0; p < 4; ++p){
                trow[2*p]   = fmaxf(lo2(acc[ii][p]), 0.f);
                trow[2*p+1] = fmaxf(hi2(acc[ii][p]), 0.f);
            }
        }
        // layer 2: K = 128
        init_acc_bias(mb2, j0, acc);
        for (int s = 0; s < 8; ++s){
            __syncthreads();
            stage_w(Ws, mw2, s * 16, 128, tid);
            __syncthreads();
            mm16<132>(T + s * 16, Ws, i0, j0, acc);
        }
        // epilogue: relu + atomic accumulate into g_agg[dst]
        #pragma unroll
        for (int ii = 0; ii < 4; ++ii){
            int i = i0 + ii;
            int p = t * 64 + i;
            if (p < cnt){
                int dst = sdst[i];
                float* arow = g_agg + (size_t)dst * HID + j0;
                #pragma unroll
                for (int q = 0; q < 4; ++q){
                    atomicAdd(arow + 2*q,     fmaxf(lo2(acc[ii][q]), 0.f));
                    atomicAdd(arow + 2*q + 1, fmaxf(hi2(acc[ii][q]), 0.f));
                }
            }
        }
    }
}

// ---------------- node update per level (only nodes with depth == lvl) ----------------
#define SMEM_UPD ((64*260 + 64*132 + 16*128) * 4 + 64 * 4)
__global__ __launch_bounds__(256, 2) void k_upd(float* __restrict__ h,
                                                const float* __restrict__ uw1, const float* __restrict__ ub1,
                                                const float* __restrict__ uw2, const float* __restrict__ ub2,
                                                int lvl){
    extern __shared__ float sm[];
    const int LDA = 260;            // K=256, pad +4
    const int LDT = 132;
    float* As = sm;                 // 64 x 260
    float* T  = As + 64 * LDA;      // 64 x 132
    float* Ws = T + 64 * LDT;       // 16 x 128
    int* snode = (int*)(Ws + 16 * HID);

    int tid = threadIdx.x;
    int ti = tid & 15, tj = tid >> 4;
    int i0 = tj << 2, j0 = ti << 3;

    int cnt  = g_ncnt[lvl];
    int base = g_noff[lvl];
    int ntiles = (cnt + 63) >> 6;

    for (int t = blockIdx.x; t < ntiles; t += gridDim.x){
        __syncthreads();
        // gather A = [h[v] | agg[v] * inv[v]]
        {
            int i = tid >> 2, sub = tid & 3;
            int p = t * 64 + i;
            int v = (p < cnt) ? g_nperm[base + p] : 0;
            float inv = g_inv[v];
            const float4* hr = (const float4*)(h + (size_t)v * HID);
            const float4* ar = (const float4*)(g_agg + (size_t)v * HID);
            #pragma unroll
            for (int c = 0; c < 8; ++c){
                int k4 = (sub << 3) + c;
                *(float4*)(As + i * LDA + (k4 << 2)) = hr[k4];
                float4 a = ar[k4];
                a.x *= inv; a.y *= inv; a.z *= inv; a.w *= inv;
                *(float4*)(As + i * LDA + 128 + (k4 << 2)) = a;
            }
            if (sub == 0) snode[i] = (p < cnt) ? v : -1;
        }
        __syncthreads();
        // layer 1: K = 256
        unsigned long long acc[4][4];
        init_acc_bias(ub1, j0, acc);
        for (int s = 0; s < 16; ++s){
            __syncthreads();
            stage_w(Ws, uw1, s * 16, 256, tid);
            __syncthreads();
            mm16<260>(As + s * 16, Ws, i0, j0, acc);
        }
        #pragma unroll
        for (int ii = 0; ii < 4; ++ii){
            float* trow = T + (i0 + ii) * LDT + j0;
            #pragma unroll
            for (int p = 0; p < 4; ++p){
                trow[2*p]   = fmaxf(lo2(acc[ii][p]), 0.f);
                trow[2*p+1] = fmaxf(hi2(acc[ii][p]), 0.f);
            }
        }
        // layer 2: K = 128
        init_acc_bias(ub2, j0, acc);
        for (int s = 0; s < 8; ++s){
            __syncthreads();
            stage_w(Ws, uw2, s * 16, 128, tid);
            __syncthreads();
            mm16<132>(T + s * 16, Ws, i0, j0, acc);
        }
        // epilogue: relu -> overwrite h[v]
        #pragma unroll
        for (int ii = 0; ii < 4; ++ii){
            int v = snode[i0 + ii];
            if (v >= 0){
                float* hr = h + (size_t)v * HID + j0;
                #pragma unroll
                for (int p = 0; p < 4; ++p)
                    *(float2*)(hr + (p << 1)) = make_float2(fmaxf(lo2(acc[ii][p]), 0.f),
                                                            fmaxf(hi2(acc[ii][p]), 0.f));
            }
        }
    }
}

// ---------------- host launch ----------------
extern "C" void kernel_launch(void* const* d_in, const int* in_sizes, int n_in,
                              void* d_out, int out_size){
    const float* x     = (const float*)d_in[0];
    const int*   ei    = (const int*)  d_in[1];
    const float* eattr = (const float*)d_in[2];
    const int*   depth = (const int*)  d_in[3];
    const float* pw    = (const float*)d_in[4];
    const float* pb    = (const float*)d_in[5];
    const float* mw1   = (const float*)d_in[6];
    const float* mb1   = (const float*)d_in[7];
    const float* mw2   = (const float*)d_in[8];
    const float* mb2   = (const float*)d_in[9];
    const float* uw1   = (const float*)d_in[10];
    const float* ub1   = (const float*)d_in[11];
    const float* uw2   = (const float*)d_in[12];
    const float* ub2   = (const float*)d_in[13];
    float* h = (float*)d_out;

    int N = in_sizes[3];       // depth has N elements
    int E = in_sizes[2];       // edge_attr has E elements (EDGE_DIM = 1)

    cudaFuncSetAttribute(k_proj, cudaFuncAttributeMaxDynamicSharedMemorySize, SMEM_PROJ);
    cudaFuncSetAttribute(k_msg,  cudaFuncAttributeMaxDynamicSharedMemorySize, SMEM_MSG);
    cudaFuncSetAttribute(k_upd,  cudaFuncAttributeMaxDynamicSharedMemorySize, SMEM_UPD);

    k_zero<<<1024, 256>>>(N * HID, N);

    int mx = (E > N) ? E : N;
    int gb = (mx + 255) / 256;
    k_count<<<gb, 256>>>(ei, depth, N, E);
    k_scan<<<1, 1>>>();
    k_scatter<<<gb, 256>>>(ei, depth, N, E);

    k_proj<<<(N + 63) / 64, 256, SMEM_PROJ>>>(x, pw, pb, h, N);

    for (int d = 1; d <= 4; ++d){
        k_msg<<<1184, 256, SMEM_MSG>>>(h, ei, eattr, mw1, mb1, mw2, mb2, E, d);
        k_upd<<<512, 256, SMEM_UPD>>>(h, uw1, ub1, uw2, ub2, d);
    }
}